// round 5
// baseline (speedup 1.0000x reference)
#include <cuda_runtime.h>
#include <math.h>
#include <stdint.h>

// Problem constants
#define BB   32
#define IDF_ 512
#define CDF_ 512
#define QQ   4096   // 64*64
#define LL   256

#define WC_ELEMS ((size_t)BB * IDF_ * QQ)

// ---------------------------------------------------------------------------
// Scratch (static device memory; no allocation at runtime)
// ---------------------------------------------------------------------------
__device__ float g_source [(size_t)BB * IDF_ * LL];   // [b][i][l]
__device__ float g_text   [(size_t)BB * IDF_ * LL];   // [b][i][l]
__device__ float g_img    [(size_t)BB * IDF_ * QQ];   // [b][o][q]
__device__ float g_attn   [(size_t)BB * QQ  * LL];    // [b][q][l]
__device__ float g_combine[(size_t)BB * QQ  * LL];    // [b][q][l]
__device__ float g_partial[BB * 16 * LL];
__device__ float g_rsums  [BB * LL];

// ---------------------------------------------------------------------------
// TF32 helpers
// ---------------------------------------------------------------------------
__device__ __forceinline__ uint32_t f2tf32(float v) {
    uint32_t r;
    asm("cvt.rna.tf32.f32 %0, %1;" : "=r"(r) : "f"(v));
    return r;
}
__device__ __forceinline__ void split_tf32(float v, uint32_t& hi, uint32_t& lo) {
    hi = f2tf32(v);
    lo = f2tf32(v - __uint_as_float(hi));
}
__device__ __forceinline__ void mma_tf32(float* c, const uint32_t* a, const uint32_t* b) {
    asm volatile(
        "mma.sync.aligned.m16n8k8.row.col.f32.tf32.tf32.f32 "
        "{%0,%1,%2,%3}, {%4,%5,%6,%7}, {%8,%9}, {%0,%1,%2,%3};"
        : "+f"(c[0]), "+f"(c[1]), "+f"(c[2]), "+f"(c[3])
        : "r"(a[0]), "r"(a[1]), "r"(a[2]), "r"(a[3]), "r"(b[0]), "r"(b[1]));
}

// ---------------------------------------------------------------------------
// Tensor-core GEMM with 3xTF32 split (fp32-equivalent accuracy).
//   C[M,N] = op(A) * B  (optionally tanh'd)
//   TRANS_A=false: A is [M,K] row-major. TRANS_A=true: A is [K,M] row-major.
//   B is [K,N] row-major. C is [M,N] row-major. All dims divide tiles.
// Block tile 128x128, K-tile 16, 8 warps (2x4), warp tile 64x32 via
// mma.sync.m16n8k8.tf32. Operands split hi/lo at staging; 3 MMAs per k8.
// Software-pipelined: next chunk's global loads are issued before the
// current chunk's MMAs so LDG latency overlaps compute.
// ---------------------------------------------------------------------------
#define AS_STRIDE 20
#define BS_STRIDE 136
// XOR swizzle on the k index of As, keyed by row bits. TN staging uses full
// 4-bit mask (conflict-free scalar transpose stores); NN uses mask 12 so
// float4 stores stay contiguous.
template <int AMASK>
__device__ __forceinline__ int as_idx(int r, int c) {
    return r * AS_STRIDE + (c ^ ((r >> 3) & AMASK));
}

template <int NSPLIT, bool TANH, bool TRANS_A>
__global__ __launch_bounds__(256, 2) void tgemm_kernel(
    const float* __restrict__ Ab, const float* __restrict__ Bb,
    float* __restrict__ Cb,
    int M, int N, int K,
    long long sA, long long sB, long long sC)
{
    constexpr int AMASK = TRANS_A ? 15 : 12;
    const float* A = Ab + (size_t)blockIdx.z * sA;
    const float* B = Bb + (size_t)blockIdx.z * sB;
    float*       C = Cb + (size_t)blockIdx.z * sC;

    __shared__ uint32_t sAh[128 * AS_STRIDE];
    __shared__ uint32_t sAl[128 * AS_STRIDE];
    __shared__ uint32_t sBh[16 * BS_STRIDE];
    __shared__ uint32_t sBl[16 * BS_STRIDE];

    const int tid  = threadIdx.x;
    const int lane = tid & 31;
    const int wid  = tid >> 5;
    const int m0   = blockIdx.y * 128;
    const int n0   = blockIdx.x * 128;
    const int wm   = (wid & 1) * 64;   // warp M offset
    const int wn   = (wid >> 1) * 32;  // warp N offset
    const int qr   = lane >> 2;        // 0..7
    const int tc   = lane & 3;         // 0..3

    // hoisted fragment-address components (constant across k loop)
    int aRow[4], aKey[4];              // for rows r = wm+16*mi+qr (and r+8)
#pragma unroll
    for (int mi = 0; mi < 4; mi++) {
        int r = wm + 16 * mi + qr;
        aRow[mi] = r * AS_STRIDE;
        aKey[mi] = (r >> 3) & AMASK;
    }
    int nIdx[4];
#pragma unroll
    for (int ni = 0; ni < 4; ni++) nIdx[ni] = wn + 8 * ni + qr;

    float acc[4][4][4];
#pragma unroll
    for (int i = 0; i < 4; i++)
#pragma unroll
        for (int j = 0; j < 4; j++)
#pragma unroll
            for (int v = 0; v < 4; v++) acc[i][j][v] = 0.f;

    // ---- global-load helper (prefetch into registers) ----
    float4 avr[2], bvr[2];
    auto load_chunk = [&](int k0) {
#pragma unroll
        for (int j = 0; j < 2; j++) {
            int idx = tid + 256 * j;
            if (!TRANS_A) {
                int r = idx >> 2, c = (idx & 3) * 4;
                avr[j] = *(const float4*)(A + (size_t)(m0 + r) * K + k0 + c);
            } else {
                int k = idx >> 5, m = (idx & 31) * 4;
                avr[j] = *(const float4*)(A + (size_t)(k0 + k) * M + m0 + m);
            }
            int k = idx >> 5, n = (idx & 31) * 4;
            bvr[j] = *(const float4*)(B + (size_t)(k0 + k) * N + n0 + n);
        }
    };

    load_chunk(0);

    for (int k0 = 0; k0 < K; k0 += 16) {
        __syncthreads();   // previous compute done reading smem
        // ---- stage registers -> smem with hi/lo split ----
#pragma unroll
        for (int j = 0; j < 2; j++) {
            int idx = tid + 256 * j;
            if (!TRANS_A) {
                int r = idx >> 2, c = (idx & 3) * 4;
                int base = as_idx<AMASK>(r, c);
                uint32_t h0,l0,h1,l1,h2,l2,h3,l3;
                split_tf32(avr[j].x, h0, l0); split_tf32(avr[j].y, h1, l1);
                split_tf32(avr[j].z, h2, l2); split_tf32(avr[j].w, h3, l3);
                *(uint4*)&sAh[base] = make_uint4(h0, h1, h2, h3);
                if (NSPLIT == 3) *(uint4*)&sAl[base] = make_uint4(l0, l1, l2, l3);
            } else {
                int k = idx >> 5, m = (idx & 31) * 4;
                float f[4] = {avr[j].x, avr[j].y, avr[j].z, avr[j].w};
#pragma unroll
                for (int u = 0; u < 4; u++) {
                    uint32_t h, l;
                    split_tf32(f[u], h, l);
                    int p = as_idx<AMASK>(m + u, k);
                    sAh[p] = h;
                    if (NSPLIT == 3) sAl[p] = l;
                }
            }
            {
                int k = idx >> 5, n = (idx & 31) * 4;
                uint32_t h0,l0,h1,l1,h2,l2,h3,l3;
                split_tf32(bvr[j].x, h0, l0); split_tf32(bvr[j].y, h1, l1);
                split_tf32(bvr[j].z, h2, l2); split_tf32(bvr[j].w, h3, l3);
                int base = k * BS_STRIDE + n;
                *(uint4*)&sBh[base] = make_uint4(h0, h1, h2, h3);
                if (NSPLIT == 3) *(uint4*)&sBl[base] = make_uint4(l0, l1, l2, l3);
            }
        }
        __syncthreads();

        // ---- prefetch next chunk (LDG latency hides under the MMAs) ----
        if (k0 + 16 < K) load_chunk(k0 + 16);

        // ---- compute: 2 k8 steps ----
#pragma unroll
        for (int ks = 0; ks < 2; ks++) {
            const int kb = ks * 8;
            uint32_t bh[4][2], bl[4][2];
#pragma unroll
            for (int ni = 0; ni < 4; ni++) {
                int n = nIdx[ni];
                bh[ni][0] = sBh[(kb + tc)     * BS_STRIDE + n];
                bh[ni][1] = sBh[(kb + tc + 4) * BS_STRIDE + n];
                if (NSPLIT == 3) {
                    bl[ni][0] = sBl[(kb + tc)     * BS_STRIDE + n];
                    bl[ni][1] = sBl[(kb + tc + 4) * BS_STRIDE + n];
                }
            }
#pragma unroll
            for (int mi = 0; mi < 4; mi++) {
                const int b0 = aRow[mi], key = aKey[mi];
                const int b1 = b0 + 8 * AS_STRIDE;      // row r+8 shares key? no:
                const int key1 = ((wm + 16 * mi + qr + 8) >> 3) & AMASK;
                uint32_t ah[4], al[4];
                ah[0] = sAh[b0 + ((kb + tc)     ^ key)];
                ah[1] = sAh[b1 + ((kb + tc)     ^ key1)];
                ah[2] = sAh[b0 + ((kb + tc + 4) ^ key)];
                ah[3] = sAh[b1 + ((kb + tc + 4) ^ key1)];
                if (NSPLIT == 3) {
                    al[0] = sAl[b0 + ((kb + tc)     ^ key)];
                    al[1] = sAl[b1 + ((kb + tc)     ^ key1)];
                    al[2] = sAl[b0 + ((kb + tc + 4) ^ key)];
                    al[3] = sAl[b1 + ((kb + tc + 4) ^ key1)];
                }
#pragma unroll
                for (int ni = 0; ni < 4; ni++) {
                    mma_tf32(acc[mi][ni], ah, bh[ni]);
                    if (NSPLIT == 3) {
                        mma_tf32(acc[mi][ni], ah, bl[ni]);
                        mma_tf32(acc[mi][ni], al, bh[ni]);
                    }
                }
            }
        }
    }

    // ---- epilogue ----
#pragma unroll
    for (int mi = 0; mi < 4; mi++) {
#pragma unroll
        for (int ni = 0; ni < 4; ni++) {
            int r0  = m0 + wm + 16 * mi + qr;
            int col = n0 + wn + 8 * ni + 2 * tc;
            float c0 = acc[mi][ni][0], c1 = acc[mi][ni][1];
            float c2 = acc[mi][ni][2], c3 = acc[mi][ni][3];
            if (TANH) { c0 = tanhf(c0); c1 = tanhf(c1); c2 = tanhf(c2); c3 = tanhf(c3); }
            *(float2*)(C + (size_t)r0 * N + col)       = make_float2(c0, c1);
            *(float2*)(C + (size_t)(r0 + 8) * N + col) = make_float2(c2, c3);
        }
    }
}

// ---------------------------------------------------------------------------
// Small FFMA SGEMM (kept for the two tiny ctx GEMMs; exact fp32).
// ---------------------------------------------------------------------------
template <bool TANH>
__global__ __launch_bounds__(256) void sgemm_kernel(
    const float* __restrict__ Ab, const float* __restrict__ Bb,
    float* __restrict__ Cb,
    int M, int N, int K,
    long long sA, long long sB, long long sC)
{
    const float* A = Ab + (size_t)blockIdx.z * sA;
    const float* B = Bb + (size_t)blockIdx.z * sB;
    float*       C = Cb + (size_t)blockIdx.z * sC;

    __shared__ float As[8][128];
    __shared__ float Bs[8][128];

    const int tid = threadIdx.x;
    const int m0  = blockIdx.y * 128;
    const int n0  = blockIdx.x * 128;
    const int tx = tid & 15;
    const int ty = tid >> 4;
    const int brow = tid >> 5;
    const int bcol = (tid & 31) * 4;
    const int arow = tid >> 1;
    const int acol = (tid & 1) * 4;

    float acc[8][8];
#pragma unroll
    for (int i = 0; i < 8; i++)
#pragma unroll
        for (int j = 0; j < 8; j++) acc[i][j] = 0.f;

    for (int k0 = 0; k0 < K; k0 += 8) {
        float4 a = *(const float4*)(A + (size_t)(m0 + arow) * K + k0 + acol);
        As[acol + 0][arow] = a.x;
        As[acol + 1][arow] = a.y;
        As[acol + 2][arow] = a.z;
        As[acol + 3][arow] = a.w;
        float4 b = *(const float4*)(B + (size_t)(k0 + brow) * N + n0 + bcol);
        *(float4*)&Bs[brow][bcol] = b;
        __syncthreads();
#pragma unroll
        for (int kk = 0; kk < 8; kk++) {
            float ar[8], br[8];
            *(float4*)&ar[0] = *(float4*)&As[kk][ty * 8];
            *(float4*)&ar[4] = *(float4*)&As[kk][ty * 8 + 4];
            *(float4*)&br[0] = *(float4*)&Bs[kk][tx * 8];
            *(float4*)&br[4] = *(float4*)&Bs[kk][tx * 8 + 4];
#pragma unroll
            for (int i = 0; i < 8; i++)
#pragma unroll
                for (int j = 0; j < 8; j++) acc[i][j] += ar[i] * br[j];
        }
        __syncthreads();
    }
#pragma unroll
    for (int i = 0; i < 8; i++) {
        size_t base = (size_t)(m0 + ty * 8 + i) * N + n0 + tx * 8;
        float4 v0, v1;
        if (TANH) {
            v0.x = tanhf(acc[i][0]); v0.y = tanhf(acc[i][1]);
            v0.z = tanhf(acc[i][2]); v0.w = tanhf(acc[i][3]);
            v1.x = tanhf(acc[i][4]); v1.y = tanhf(acc[i][5]);
            v1.z = tanhf(acc[i][6]); v1.w = tanhf(acc[i][7]);
        } else {
            v0.x = acc[i][0]; v0.y = acc[i][1]; v0.z = acc[i][2]; v0.w = acc[i][3];
            v1.x = acc[i][4]; v1.y = acc[i][5]; v1.z = acc[i][6]; v1.w = acc[i][7];
        }
        *(float4*)(C + base)     = v0;
        *(float4*)(C + base + 4) = v1;
    }
}

// ---------------------------------------------------------------------------
// Softmax over L=256 (in place), one block per row.
// ---------------------------------------------------------------------------
__global__ __launch_bounds__(256) void softmax_rows256(float* __restrict__ data)
{
    const size_t row = blockIdx.x;
    const int t = threadIdx.x;
    float v = data[row * LL + t];

    __shared__ float red[8];
    float m = v;
#pragma unroll
    for (int o = 16; o; o >>= 1) m = fmaxf(m, __shfl_xor_sync(0xffffffffu, m, o));
    if ((t & 31) == 0) red[t >> 5] = m;
    __syncthreads();
    if (t < 8) {
        float x = red[t];
#pragma unroll
        for (int o = 4; o; o >>= 1) x = fmaxf(x, __shfl_xor_sync(0xffu, x, o));
        if (t == 0) red[0] = x;
    }
    __syncthreads();
    m = red[0];
    float e = expf(v - m);
    __syncthreads();
    float s = e;
#pragma unroll
    for (int o = 16; o; o >>= 1) s += __shfl_xor_sync(0xffffffffu, s, o);
    if ((t & 31) == 0) red[t >> 5] = s;
    __syncthreads();
    if (t < 8) {
        float x = red[t];
#pragma unroll
        for (int o = 4; o; o >>= 1) x += __shfl_xor_sync(0xffu, x, o);
        if (t == 0) red[0] = x;
    }
    __syncthreads();
    data[row * LL + t] = e / red[0];
}

// ---------------------------------------------------------------------------
// Second softmax (over Q): partial sum-exp, reduce to reciprocal.
// ---------------------------------------------------------------------------
__global__ __launch_bounds__(256) void sumexp_partial_kernel()
{
    const int b = blockIdx.x;
    const int chunk = blockIdx.y;
    const int l = threadIdx.x;
    const size_t base = ((size_t)b * QQ + (size_t)chunk * 256) * LL + l;
    float s = 0.f;
#pragma unroll 8
    for (int q = 0; q < 256; q++) s += expf(g_attn[base + (size_t)q * LL]);
    g_partial[(b * 16 + chunk) * LL + l] = s;
}

__global__ __launch_bounds__(256) void sumexp_reduce_kernel()
{
    const int b = blockIdx.x;
    const int l = threadIdx.x;
    float s = 0.f;
#pragma unroll
    for (int c = 0; c < 16; c++) s += g_partial[(b * 16 + c) * LL + l];
    g_rsums[b * LL + l] = 1.0f / s;
}

// ---------------------------------------------------------------------------
// Finalize: exp * (1/sum) * combine, transposed into attn_map [b][l][q].
// ---------------------------------------------------------------------------
__global__ __launch_bounds__(256) void finalize_kernel(float* __restrict__ out_am)
{
    const int b  = blockIdx.y;
    const int q0 = blockIdx.x * 32;
    const int tx = threadIdx.x;
    const int ty = threadIdx.y;

    __shared__ float tile[32][33];

    for (int l0 = 0; l0 < LL; l0 += 32) {
        const float rs_col = g_rsums[b * LL + l0 + tx];
#pragma unroll
        for (int r = 0; r < 4; r++) {
            const int q = q0 + ty + 8 * r;
            const size_t idx = ((size_t)b * QQ + q) * LL + l0 + tx;
            tile[ty + 8 * r][tx] = expf(g_attn[idx]) * rs_col * g_combine[idx];
        }
        __syncthreads();
#pragma unroll
        for (int r = 0; r < 4; r++) {
            const int l = l0 + ty + 8 * r;
            out_am[((size_t)b * LL + l) * QQ + q0 + tx] = tile[tx][ty + 8 * r];
        }
        __syncthreads();
    }
}

// ---------------------------------------------------------------------------
// Launcher
// ---------------------------------------------------------------------------
extern "C" void kernel_launch(void* const* d_in, const int* in_sizes, int n_in,
                              void* d_out, int out_size)
{
    const float* x         = (const float*)d_in[0];
    const float* context   = (const float*)d_in[1];
    const float* w_context = (const float*)d_in[2];
    const float* w_img     = (const float*)d_in[3];
    const float* w_text    = (const float*)d_in[4];

    float* out_wc = (float*)d_out;
    float* out_am = out_wc + WC_ELEMS;

    float *p_source, *p_text, *p_img, *p_attn, *p_combine;
    cudaGetSymbolAddress((void**)&p_source,  g_source);
    cudaGetSymbolAddress((void**)&p_text,    g_text);
    cudaGetSymbolAddress((void**)&p_img,     g_img);
    cudaGetSymbolAddress((void**)&p_attn,    g_attn);
    cudaGetSymbolAddress((void**)&p_combine, g_combine);

    const long long sCTX = (long long)CDF_ * LL;
    const long long sSL  = (long long)IDF_ * LL;
    const long long sIQ  = (long long)IDF_ * QQ;
    const long long sQL  = (long long)QQ * LL;

    // 1) source = W_ctx @ ctx (exact fp32, feeds attn logits)
    sgemm_kernel<false><<<dim3(2, 4, BB), 256>>>(
        w_context, context, p_source, IDF_, LL, CDF_, 0, sCTX, sSL);
    // 2) text = tanh(W_text @ ctx)
    sgemm_kernel<true><<<dim3(2, 4, BB), 256>>>(
        w_text, context, p_text, IDF_, LL, CDF_, 0, sCTX, sSL);
    // 3) img = tanh(W_img @ x)  — tensor, 3xTF32, pipelined
    tgemm_kernel<3, true, false><<<dim3(32, 4, BB), 256>>>(
        w_img, x, p_img, IDF_, QQ, IDF_, 0, sIQ, sIQ);
    // 4) attn = x^T @ source    — tensor, 3xTF32, pipelined
    tgemm_kernel<3, false, true><<<dim3(2, 32, BB), 256>>>(
        x, p_source, p_attn, QQ, LL, IDF_, sIQ, sSL, sQL);
    // 5) combine = tanh(img^T @ text) — tensor, 3xTF32, pipelined
    tgemm_kernel<3, true, true><<<dim3(2, 32, BB), 256>>>(
        p_img, p_text, p_combine, QQ, LL, IDF_, sIQ, sSL, sQL);
    // 6) softmax over L
    softmax_rows256<<<BB * QQ, 256>>>(p_attn);
    // 7) second softmax over Q
    sumexp_partial_kernel<<<dim3(BB, 16), 256>>>();
    sumexp_reduce_kernel<<<BB, 256>>>();
    // 8) finalize into attn_map [b][l][q]
    finalize_kernel<<<dim3(QQ / 32, BB), dim3(32, 8)>>>(out_am);
    // 9) weighted_context = source @ attn_map — tensor, 3xTF32, pipelined
    tgemm_kernel<3, false, false><<<dim3(32, 4, BB), 256>>>(
        p_source, out_am, out_wc, IDF_, QQ, LL, sSL, (long long)LL * QQ, sIQ);
}

// round 6
// speedup vs baseline: 1.2826x; 1.2826x over previous
#include <cuda_runtime.h>
#include <math.h>
#include <stdint.h>

// Problem constants
#define BB   32
#define IDF_ 512
#define CDF_ 512
#define QQ   4096   // 64*64
#define LL   256

#define WC_ELEMS ((size_t)BB * IDF_ * QQ)

// ---------------------------------------------------------------------------
// Scratch (static device memory; no allocation at runtime)
// ---------------------------------------------------------------------------
__device__ float g_source [(size_t)BB * IDF_ * LL];   // [b][i][l]
__device__ float g_text   [(size_t)BB * IDF_ * LL];   // [b][i][l]
__device__ float g_img    [(size_t)BB * IDF_ * QQ];   // [b][o][q]
__device__ float g_attn   [(size_t)BB * QQ  * LL];    // [b][q][l]
__device__ float g_combine[(size_t)BB * QQ  * LL];    // [b][q][l]
__device__ float g_partial[BB * 16 * LL];
__device__ float g_rsums  [BB * LL];

// ---------------------------------------------------------------------------
// TF32 helpers
// ---------------------------------------------------------------------------
__device__ __forceinline__ uint32_t f2tf32(float v) {
    uint32_t r;
    asm("cvt.rna.tf32.f32 %0, %1;" : "=r"(r) : "f"(v));
    return r;
}
__device__ __forceinline__ void split_tf32(float v, uint32_t& hi, uint32_t& lo) {
    hi = f2tf32(v);
    lo = f2tf32(v - __uint_as_float(hi));
}
__device__ __forceinline__ void mma_tf32(float* c, const uint32_t* a, const uint32_t* b) {
    asm volatile(
        "mma.sync.aligned.m16n8k8.row.col.f32.tf32.tf32.f32 "
        "{%0,%1,%2,%3}, {%4,%5,%6,%7}, {%8,%9}, {%0,%1,%2,%3};"
        : "+f"(c[0]), "+f"(c[1]), "+f"(c[2]), "+f"(c[3])
        : "r"(a[0]), "r"(a[1]), "r"(a[2]), "r"(a[3]), "r"(b[0]), "r"(b[1]));
}

__device__ __forceinline__ void cp_async16(uint32_t smem_dst, const void* gsrc) {
    asm volatile("cp.async.cg.shared.global [%0], [%1], 16;"
                 :: "r"(smem_dst), "l"(gsrc) : "memory");
}
#define CP_COMMIT() asm volatile("cp.async.commit_group;" ::: "memory")
#define CP_WAIT(n)  asm volatile("cp.async.wait_group %0;" :: "n"(n) : "memory")

// ---------------------------------------------------------------------------
// Tensor-core GEMM, 3xTF32 split (fp32-equivalent), cp.async double-buffered.
//   C[M,N] = op(A) * B  (optionally tanh'd)
//   TRANS_A=false: A [M,K] row-major, staged as [m][k] stride 20, XOR-12 swizzle.
//   TRANS_A=true : A [K,M] row-major, staged as [k][m] stride 136.
//   B [K,N] row-major, staged as [k][n] stride 136. C row-major.
// Block tile 128x128, K-tile 16, 8 warps (2x4), warp tile 64x32,
// mma.sync.m16n8k8.tf32. Raw fp32 in smem; hi/lo split at fragment read.
// ---------------------------------------------------------------------------
#define AS_STRIDE 20
#define BS_STRIDE 136

template <bool TANH, bool TRANS_A>
__global__ __launch_bounds__(256, 2) void tgemm_kernel(
    const float* __restrict__ Ab, const float* __restrict__ Bb,
    float* __restrict__ Cb,
    int M, int N, int K,
    long long sA, long long sB, long long sC)
{
    constexpr int ASZ = TRANS_A ? (16 * BS_STRIDE) : (128 * AS_STRIDE);
    const float* A = Ab + (size_t)blockIdx.z * sA;
    const float* B = Bb + (size_t)blockIdx.z * sB;
    float*       C = Cb + (size_t)blockIdx.z * sC;

    __shared__ float sAs[2][ASZ];
    __shared__ float sBs[2][16 * BS_STRIDE];

    const int tid  = threadIdx.x;
    const int lane = tid & 31;
    const int wid  = tid >> 5;
    const int m0   = blockIdx.y * 128;
    const int n0   = blockIdx.x * 128;
    const int wm   = (wid & 1) * 64;   // warp M offset
    const int wn   = (wid >> 1) * 32;  // warp N offset
    const int qr   = lane >> 2;        // 0..7
    const int tc   = lane & 3;         // 0..3

    float acc[4][4][4];
#pragma unroll
    for (int i = 0; i < 4; i++)
#pragma unroll
        for (int j = 0; j < 4; j++)
#pragma unroll
            for (int v = 0; v < 4; v++) acc[i][j][v] = 0.f;

    // smem base addresses (u32) for cp.async
    uint32_t aBase[2], bBase[2];
#pragma unroll
    for (int p = 0; p < 2; p++) {
        aBase[p] = (uint32_t)__cvta_generic_to_shared(&sAs[p][0]);
        bBase[p] = (uint32_t)__cvta_generic_to_shared(&sBs[p][0]);
    }

    // ---- async stage of one K-chunk into stage p ----
    auto issue_chunk = [&](int k0, int p) {
#pragma unroll
        for (int j = 0; j < 2; j++) {
            int idx = tid + 256 * j;
            if (!TRANS_A) {
                int r = idx >> 2, c = (idx & 3) * 4;
                int dst = r * AS_STRIDE + (c ^ ((r >> 3) & 12));
                cp_async16(aBase[p] + 4 * dst, A + (size_t)(m0 + r) * K + k0 + c);
            } else {
                int k = idx >> 5, m = (idx & 31) * 4;
                cp_async16(aBase[p] + 4 * (k * BS_STRIDE + m),
                           A + (size_t)(k0 + k) * M + m0 + m);
            }
            int k = idx >> 5, n = (idx & 31) * 4;
            cp_async16(bBase[p] + 4 * (k * BS_STRIDE + n),
                       B + (size_t)(k0 + k) * N + n0 + n);
        }
        CP_COMMIT();
    };

    const int nchunk = K >> 4;
    issue_chunk(0, 0);

    for (int c = 0; c < nchunk; c++) {
        const int p = c & 1;
        const bool more = (c + 1 < nchunk);
        if (more) issue_chunk((c + 1) << 4, p ^ 1);
        if (more) CP_WAIT(1); else CP_WAIT(0);
        __syncthreads();

        const float* sa = sAs[p];
        const float* sb = sBs[p];
#pragma unroll
        for (int ks = 0; ks < 2; ks++) {
            const int kb = ks * 8;
            // B fragments (shared across mi): split at read
            uint32_t bh[4][2], bl[4][2];
#pragma unroll
            for (int ni = 0; ni < 4; ni++) {
                int n = wn + 8 * ni + qr;
                split_tf32(sb[(kb + tc)     * BS_STRIDE + n], bh[ni][0], bl[ni][0]);
                split_tf32(sb[(kb + tc + 4) * BS_STRIDE + n], bh[ni][1], bl[ni][1]);
            }
#pragma unroll
            for (int mi = 0; mi < 4; mi++) {
                const int r = wm + 16 * mi + qr;
                uint32_t ah[4], al[4];
                if (!TRANS_A) {
                    const int key0 = (r >> 3) & 12;
                    const int key1 = ((r + 8) >> 3) & 12;
                    split_tf32(sa[r * AS_STRIDE       + ((kb + tc)     ^ key0)], ah[0], al[0]);
                    split_tf32(sa[(r + 8) * AS_STRIDE + ((kb + tc)     ^ key1)], ah[1], al[1]);
                    split_tf32(sa[r * AS_STRIDE       + ((kb + tc + 4) ^ key0)], ah[2], al[2]);
                    split_tf32(sa[(r + 8) * AS_STRIDE + ((kb + tc + 4) ^ key1)], ah[3], al[3]);
                } else {
                    split_tf32(sa[(kb + tc)     * BS_STRIDE + r],     ah[0], al[0]);
                    split_tf32(sa[(kb + tc)     * BS_STRIDE + r + 8], ah[1], al[1]);
                    split_tf32(sa[(kb + tc + 4) * BS_STRIDE + r],     ah[2], al[2]);
                    split_tf32(sa[(kb + tc + 4) * BS_STRIDE + r + 8], ah[3], al[3]);
                }
#pragma unroll
                for (int ni = 0; ni < 4; ni++) {
                    mma_tf32(acc[mi][ni], ah, bh[ni]);
                    mma_tf32(acc[mi][ni], ah, bl[ni]);
                    mma_tf32(acc[mi][ni], al, bh[ni]);
                }
            }
        }
        __syncthreads();   // done reading stage p before it is re-filled
    }

    // ---- epilogue ----
#pragma unroll
    for (int mi = 0; mi < 4; mi++) {
#pragma unroll
        for (int ni = 0; ni < 4; ni++) {
            int r0  = m0 + wm + 16 * mi + qr;
            int col = n0 + wn + 8 * ni + 2 * tc;
            float c0 = acc[mi][ni][0], c1 = acc[mi][ni][1];
            float c2 = acc[mi][ni][2], c3 = acc[mi][ni][3];
            if (TANH) { c0 = tanhf(c0); c1 = tanhf(c1); c2 = tanhf(c2); c3 = tanhf(c3); }
            *(float2*)(C + (size_t)r0 * N + col)       = make_float2(c0, c1);
            *(float2*)(C + (size_t)(r0 + 8) * N + col) = make_float2(c2, c3);
        }
    }
}

// ---------------------------------------------------------------------------
// Small FFMA SGEMM (two tiny ctx GEMMs; exact fp32).
// ---------------------------------------------------------------------------
template <bool TANH>
__global__ __launch_bounds__(256) void sgemm_kernel(
    const float* __restrict__ Ab, const float* __restrict__ Bb,
    float* __restrict__ Cb,
    int M, int N, int K,
    long long sA, long long sB, long long sC)
{
    const float* A = Ab + (size_t)blockIdx.z * sA;
    const float* B = Bb + (size_t)blockIdx.z * sB;
    float*       C = Cb + (size_t)blockIdx.z * sC;

    __shared__ float As[8][128];
    __shared__ float Bs[8][128];

    const int tid = threadIdx.x;
    const int m0  = blockIdx.y * 128;
    const int n0  = blockIdx.x * 128;
    const int tx = tid & 15;
    const int ty = tid >> 4;
    const int brow = tid >> 5;
    const int bcol = (tid & 31) * 4;
    const int arow = tid >> 1;
    const int acol = (tid & 1) * 4;

    float acc[8][8];
#pragma unroll
    for (int i = 0; i < 8; i++)
#pragma unroll
        for (int j = 0; j < 8; j++) acc[i][j] = 0.f;

    for (int k0 = 0; k0 < K; k0 += 8) {
        float4 a = *(const float4*)(A + (size_t)(m0 + arow) * K + k0 + acol);
        As[acol + 0][arow] = a.x;
        As[acol + 1][arow] = a.y;
        As[acol + 2][arow] = a.z;
        As[acol + 3][arow] = a.w;
        float4 b = *(const float4*)(B + (size_t)(k0 + brow) * N + n0 + bcol);
        *(float4*)&Bs[brow][bcol] = b;
        __syncthreads();
#pragma unroll
        for (int kk = 0; kk < 8; kk++) {
            float ar[8], br[8];
            *(float4*)&ar[0] = *(float4*)&As[kk][ty * 8];
            *(float4*)&ar[4] = *(float4*)&As[kk][ty * 8 + 4];
            *(float4*)&br[0] = *(float4*)&Bs[kk][tx * 8];
            *(float4*)&br[4] = *(float4*)&Bs[kk][tx * 8 + 4];
#pragma unroll
            for (int i = 0; i < 8; i++)
#pragma unroll
                for (int j = 0; j < 8; j++) acc[i][j] += ar[i] * br[j];
        }
        __syncthreads();
    }
#pragma unroll
    for (int i = 0; i < 8; i++) {
        size_t base = (size_t)(m0 + ty * 8 + i) * N + n0 + tx * 8;
        float4 v0, v1;
        if (TANH) {
            v0.x = tanhf(acc[i][0]); v0.y = tanhf(acc[i][1]);
            v0.z = tanhf(acc[i][2]); v0.w = tanhf(acc[i][3]);
            v1.x = tanhf(acc[i][4]); v1.y = tanhf(acc[i][5]);
            v1.z = tanhf(acc[i][6]); v1.w = tanhf(acc[i][7]);
        } else {
            v0.x = acc[i][0]; v0.y = acc[i][1]; v0.z = acc[i][2]; v0.w = acc[i][3];
            v1.x = acc[i][4]; v1.y = acc[i][5]; v1.z = acc[i][6]; v1.w = acc[i][7];
        }
        *(float4*)(C + base)     = v0;
        *(float4*)(C + base + 4) = v1;
    }
}

// ---------------------------------------------------------------------------
// Softmax over L=256 (in place), one block per row.
// ---------------------------------------------------------------------------
__global__ __launch_bounds__(256) void softmax_rows256(float* __restrict__ data)
{
    const size_t row = blockIdx.x;
    const int t = threadIdx.x;
    float v = data[row * LL + t];

    __shared__ float red[8];
    float m = v;
#pragma unroll
    for (int o = 16; o; o >>= 1) m = fmaxf(m, __shfl_xor_sync(0xffffffffu, m, o));
    if ((t & 31) == 0) red[t >> 5] = m;
    __syncthreads();
    if (t < 8) {
        float x = red[t];
#pragma unroll
        for (int o = 4; o; o >>= 1) x = fmaxf(x, __shfl_xor_sync(0xffu, x, o));
        if (t == 0) red[0] = x;
    }
    __syncthreads();
    m = red[0];
    float e = expf(v - m);
    __syncthreads();
    float s = e;
#pragma unroll
    for (int o = 16; o; o >>= 1) s += __shfl_xor_sync(0xffffffffu, s, o);
    if ((t & 31) == 0) red[t >> 5] = s;
    __syncthreads();
    if (t < 8) {
        float x = red[t];
#pragma unroll
        for (int o = 4; o; o >>= 1) x += __shfl_xor_sync(0xffu, x, o);
        if (t == 0) red[0] = x;
    }
    __syncthreads();
    data[row * LL + t] = e / red[0];
}

// ---------------------------------------------------------------------------
// Second softmax (over Q): partial sum-exp, reduce to reciprocal.
// ---------------------------------------------------------------------------
__global__ __launch_bounds__(256) void sumexp_partial_kernel()
{
    const int b = blockIdx.x;
    const int chunk = blockIdx.y;
    const int l = threadIdx.x;
    const size_t base = ((size_t)b * QQ + (size_t)chunk * 256) * LL + l;
    float s = 0.f;
#pragma unroll 8
    for (int q = 0; q < 256; q++) s += expf(g_attn[base + (size_t)q * LL]);
    g_partial[(b * 16 + chunk) * LL + l] = s;
}

__global__ __launch_bounds__(256) void sumexp_reduce_kernel()
{
    const int b = blockIdx.x;
    const int l = threadIdx.x;
    float s = 0.f;
#pragma unroll
    for (int c = 0; c < 16; c++) s += g_partial[(b * 16 + c) * LL + l];
    g_rsums[b * LL + l] = 1.0f / s;
}

// ---------------------------------------------------------------------------
// Finalize: exp * (1/sum) * combine, transposed into attn_map [b][l][q].
// ---------------------------------------------------------------------------
__global__ __launch_bounds__(256) void finalize_kernel(float* __restrict__ out_am)
{
    const int b  = blockIdx.y;
    const int q0 = blockIdx.x * 32;
    const int tx = threadIdx.x;
    const int ty = threadIdx.y;

    __shared__ float tile[32][33];

    for (int l0 = 0; l0 < LL; l0 += 32) {
        const float rs_col = g_rsums[b * LL + l0 + tx];
#pragma unroll
        for (int r = 0; r < 4; r++) {
            const int q = q0 + ty + 8 * r;
            const size_t idx = ((size_t)b * QQ + q) * LL + l0 + tx;
            tile[ty + 8 * r][tx] = expf(g_attn[idx]) * rs_col * g_combine[idx];
        }
        __syncthreads();
#pragma unroll
        for (int r = 0; r < 4; r++) {
            const int l = l0 + ty + 8 * r;
            out_am[((size_t)b * LL + l) * QQ + q0 + tx] = tile[tx][ty + 8 * r];
        }
        __syncthreads();
    }
}

// ---------------------------------------------------------------------------
// Launcher
// ---------------------------------------------------------------------------
extern "C" void kernel_launch(void* const* d_in, const int* in_sizes, int n_in,
                              void* d_out, int out_size)
{
    const float* x         = (const float*)d_in[0];
    const float* context   = (const float*)d_in[1];
    const float* w_context = (const float*)d_in[2];
    const float* w_img     = (const float*)d_in[3];
    const float* w_text    = (const float*)d_in[4];

    float* out_wc = (float*)d_out;
    float* out_am = out_wc + WC_ELEMS;

    float *p_source, *p_text, *p_img, *p_attn, *p_combine;
    cudaGetSymbolAddress((void**)&p_source,  g_source);
    cudaGetSymbolAddress((void**)&p_text,    g_text);
    cudaGetSymbolAddress((void**)&p_img,     g_img);
    cudaGetSymbolAddress((void**)&p_attn,    g_attn);
    cudaGetSymbolAddress((void**)&p_combine, g_combine);

    const long long sCTX = (long long)CDF_ * LL;
    const long long sSL  = (long long)IDF_ * LL;
    const long long sIQ  = (long long)IDF_ * QQ;
    const long long sQL  = (long long)QQ * LL;

    // 1) source = W_ctx @ ctx (exact fp32, feeds attn logits)
    sgemm_kernel<false><<<dim3(2, 4, BB), 256>>>(
        w_context, context, p_source, IDF_, LL, CDF_, 0, sCTX, sSL);
    // 2) text = tanh(W_text @ ctx)
    sgemm_kernel<true><<<dim3(2, 4, BB), 256>>>(
        w_text, context, p_text, IDF_, LL, CDF_, 0, sCTX, sSL);
    // 3) img = tanh(W_img @ x)  — tensor, 3xTF32, cp.async pipelined
    tgemm_kernel<true, false><<<dim3(32, 4, BB), 256>>>(
        w_img, x, p_img, IDF_, QQ, IDF_, 0, sIQ, sIQ);
    // 4) attn = x^T @ source    — tensor, 3xTF32, cp.async pipelined
    tgemm_kernel<false, true><<<dim3(2, 32, BB), 256>>>(
        x, p_source, p_attn, QQ, LL, IDF_, sIQ, sSL, sQL);
    // 5) combine = tanh(img^T @ text)
    tgemm_kernel<true, true><<<dim3(2, 32, BB), 256>>>(
        p_img, p_text, p_combine, QQ, LL, IDF_, sIQ, sSL, sQL);
    // 6) softmax over L
    softmax_rows256<<<BB * QQ, 256>>>(p_attn);
    // 7) second softmax over Q
    sumexp_partial_kernel<<<dim3(BB, 16), 256>>>();
    sumexp_reduce_kernel<<<BB, 256>>>();
    // 8) finalize into attn_map [b][l][q]
    finalize_kernel<<<dim3(QQ / 32, BB), dim3(32, 8)>>>(out_am);
    // 9) weighted_context = source @ attn_map
    tgemm_kernel<false, false><<<dim3(32, 4, BB), 256>>>(
        p_source, out_am, out_wc, IDF_, QQ, LL, sSL, (long long)LL * QQ, sIQ);
}

// round 7
// speedup vs baseline: 1.8964x; 1.4785x over previous
#include <cuda_runtime.h>
#include <cuda_fp16.h>
#include <math.h>
#include <stdint.h>

// Problem constants
#define BB   32
#define IDF_ 512
#define CDF_ 512
#define QQ   4096   // 64*64
#define LL   256

#define WC_ELEMS ((size_t)BB * IDF_ * QQ)

// ---------------------------------------------------------------------------
// Scratch (static device memory; no allocation at runtime)
// ---------------------------------------------------------------------------
__device__ float g_source [(size_t)BB * IDF_ * LL];   // [b][i][l]
__device__ float g_text   [(size_t)BB * IDF_ * LL];   // [b][i][l]
__device__ float g_img    [(size_t)BB * IDF_ * QQ];   // [b][o][q]
__device__ float g_attn   [(size_t)BB * QQ  * LL];    // [b][q][l]
__device__ float g_combine[(size_t)BB * QQ  * LL];    // [b][q][l]
__device__ float g_partial[BB * 16 * LL];
__device__ float g_rsums  [BB * LL];

// ---------------------------------------------------------------------------
// FP16 Markidis-split helpers: v = hi + lo, each fp16 (11-bit mantissa), so
// hh + hl + lh with fp32 accumulation is fp32-equivalent (error ~2^-22).
// split2 packs two consecutive elements into f16x2 fragment registers.
// ---------------------------------------------------------------------------
__device__ __forceinline__ void split2_f16(float v0, float v1,
                                           uint32_t& hi, uint32_t& lo) {
    __half2 h = __floats2half2_rn(v0, v1);
    float2 hf = __half22float2(h);
    __half2 l = __floats2half2_rn(v0 - hf.x, v1 - hf.y);
    hi = *(uint32_t*)&h;
    lo = *(uint32_t*)&l;
}

__device__ __forceinline__ void mma_f16(float* c, const uint32_t* a, const uint32_t* b) {
    asm volatile(
        "mma.sync.aligned.m16n8k16.row.col.f32.f16.f16.f32 "
        "{%0,%1,%2,%3}, {%4,%5,%6,%7}, {%8,%9}, {%0,%1,%2,%3};"
        : "+f"(c[0]), "+f"(c[1]), "+f"(c[2]), "+f"(c[3])
        : "r"(a[0]), "r"(a[1]), "r"(a[2]), "r"(a[3]), "r"(b[0]), "r"(b[1]));
}

__device__ __forceinline__ void cp_async16(uint32_t smem_dst, const void* gsrc) {
    asm volatile("cp.async.cg.shared.global [%0], [%1], 16;"
                 :: "r"(smem_dst), "l"(gsrc) : "memory");
}
#define CP_COMMIT() asm volatile("cp.async.commit_group;" ::: "memory")
#define CP_WAIT(n)  asm volatile("cp.async.wait_group %0;" :: "n"(n) : "memory")

// ---------------------------------------------------------------------------
// Tensor-core GEMM, 3xFP16 split (fp32-equivalent), cp.async double-buffered.
//   C[M,N] = op(A) * B  (optionally tanh'd)
//   TRANS_A=false: A [M,K] row-major, staged [m][k] stride 20, XOR-12 swizzle.
//   TRANS_A=true : A [K,M] row-major, staged [k][m] stride 132.
//   B [K,N] row-major, staged [k][n] stride 132. C row-major.
// Block tile 128x128, K-tile 16, 8 warps (2x4), warp tile 64x32,
// mma.sync.m16n8k16.f16 (3 MMAs per k16). Raw fp32 in smem; split at read.
// ---------------------------------------------------------------------------
#define AS_STRIDE 20
#define BS_STRIDE 132   // 2k-row fragment reads hit distinct banks ({0,8,16,24})

template <bool TANH, bool TRANS_A>
__global__ __launch_bounds__(256, 2) void tgemm_kernel(
    const float* __restrict__ Ab, const float* __restrict__ Bb,
    float* __restrict__ Cb,
    int M, int N, int K,
    long long sA, long long sB, long long sC)
{
    constexpr int ASZ = TRANS_A ? (16 * BS_STRIDE) : (128 * AS_STRIDE);
    const float* A = Ab + (size_t)blockIdx.z * sA;
    const float* B = Bb + (size_t)blockIdx.z * sB;
    float*       C = Cb + (size_t)blockIdx.z * sC;

    __shared__ __align__(16) float sAs[2][ASZ];
    __shared__ __align__(16) float sBs[2][16 * BS_STRIDE];

    const int tid  = threadIdx.x;
    const int lane = tid & 31;
    const int wid  = tid >> 5;
    const int m0   = blockIdx.y * 128;
    const int n0   = blockIdx.x * 128;
    const int wm   = (wid & 1) * 64;   // warp M offset
    const int wn   = (wid >> 1) * 32;  // warp N offset
    const int qr   = lane >> 2;        // 0..7
    const int tc   = lane & 3;         // 0..3

    float acc[4][4][4];
#pragma unroll
    for (int i = 0; i < 4; i++)
#pragma unroll
        for (int j = 0; j < 4; j++)
#pragma unroll
            for (int v = 0; v < 4; v++) acc[i][j][v] = 0.f;

    uint32_t aBase[2], bBase[2];
#pragma unroll
    for (int p = 0; p < 2; p++) {
        aBase[p] = (uint32_t)__cvta_generic_to_shared(&sAs[p][0]);
        bBase[p] = (uint32_t)__cvta_generic_to_shared(&sBs[p][0]);
    }

    // ---- async stage of one K-chunk (16) into stage p ----
    auto issue_chunk = [&](int k0, int p) {
#pragma unroll
        for (int j = 0; j < 2; j++) {
            int idx = tid + 256 * j;
            if (!TRANS_A) {
                int r = idx >> 2, c = (idx & 3) * 4;
                int dst = r * AS_STRIDE + (c ^ ((r >> 3) & 12));
                cp_async16(aBase[p] + 4 * dst, A + (size_t)(m0 + r) * K + k0 + c);
            } else {
                int k = idx >> 5, m = (idx & 31) * 4;
                cp_async16(aBase[p] + 4 * (k * BS_STRIDE + m),
                           A + (size_t)(k0 + k) * M + m0 + m);
            }
            int k = idx >> 5, n = (idx & 31) * 4;
            cp_async16(bBase[p] + 4 * (k * BS_STRIDE + n),
                       B + (size_t)(k0 + k) * N + n0 + n);
        }
        CP_COMMIT();
    };

    const int nchunk = K >> 4;
    issue_chunk(0, 0);

    for (int c = 0; c < nchunk; c++) {
        const int p = c & 1;
        const bool more = (c + 1 < nchunk);
        if (more) issue_chunk((c + 1) << 4, p ^ 1);
        if (more) CP_WAIT(1); else CP_WAIT(0);
        __syncthreads();

        const float* sa = sAs[p];
        const float* sb = sBs[p];

        // ---- B fragments (m16n8k16: k-pairs {2tc,2tc+1} and {2tc+8,2tc+9}) ----
        uint32_t bh[4][2], bl[4][2];
#pragma unroll
        for (int ni = 0; ni < 4; ni++) {
            int n = wn + 8 * ni + qr;
            split2_f16(sb[(2 * tc)     * BS_STRIDE + n],
                       sb[(2 * tc + 1) * BS_STRIDE + n], bh[ni][0], bl[ni][0]);
            split2_f16(sb[(2 * tc + 8) * BS_STRIDE + n],
                       sb[(2 * tc + 9) * BS_STRIDE + n], bh[ni][1], bl[ni][1]);
        }
#pragma unroll
        for (int mi = 0; mi < 4; mi++) {
            const int r = wm + 16 * mi + qr;
            uint32_t ah[4], al[4];
            if (!TRANS_A) {
                // key flips bits 2,3 only -> (2tc)^key stays even: float2 loads ok
                const int key0 = (r >> 3) & 12;
                const int key1 = ((r + 8) >> 3) & 12;
                float2 p0 = *(const float2*)&sa[r * AS_STRIDE       + ((2 * tc)     ^ key0)];
                float2 p1 = *(const float2*)&sa[(r + 8) * AS_STRIDE + ((2 * tc)     ^ key1)];
                float2 p2 = *(const float2*)&sa[r * AS_STRIDE       + ((2 * tc + 8) ^ key0)];
                float2 p3 = *(const float2*)&sa[(r + 8) * AS_STRIDE + ((2 * tc + 8) ^ key1)];
                split2_f16(p0.x, p0.y, ah[0], al[0]);
                split2_f16(p1.x, p1.y, ah[1], al[1]);
                split2_f16(p2.x, p2.y, ah[2], al[2]);
                split2_f16(p3.x, p3.y, ah[3], al[3]);
            } else {
                split2_f16(sa[(2 * tc)     * BS_STRIDE + r],
                           sa[(2 * tc + 1) * BS_STRIDE + r],     ah[0], al[0]);
                split2_f16(sa[(2 * tc)     * BS_STRIDE + r + 8],
                           sa[(2 * tc + 1) * BS_STRIDE + r + 8], ah[1], al[1]);
                split2_f16(sa[(2 * tc + 8) * BS_STRIDE + r],
                           sa[(2 * tc + 9) * BS_STRIDE + r],     ah[2], al[2]);
                split2_f16(sa[(2 * tc + 8) * BS_STRIDE + r + 8],
                           sa[(2 * tc + 9) * BS_STRIDE + r + 8], ah[3], al[3]);
            }
#pragma unroll
            for (int ni = 0; ni < 4; ni++) {
                mma_f16(acc[mi][ni], ah, bh[ni]);
                mma_f16(acc[mi][ni], ah, bl[ni]);
                mma_f16(acc[mi][ni], al, bh[ni]);
            }
        }
        __syncthreads();   // done reading stage p before it is re-filled
    }

    // ---- epilogue (C fragment layout identical to m16n8k8) ----
#pragma unroll
    for (int mi = 0; mi < 4; mi++) {
#pragma unroll
        for (int ni = 0; ni < 4; ni++) {
            int r0  = m0 + wm + 16 * mi + qr;
            int col = n0 + wn + 8 * ni + 2 * tc;
            float c0 = acc[mi][ni][0], c1 = acc[mi][ni][1];
            float c2 = acc[mi][ni][2], c3 = acc[mi][ni][3];
            if (TANH) { c0 = tanhf(c0); c1 = tanhf(c1); c2 = tanhf(c2); c3 = tanhf(c3); }
            *(float2*)(C + (size_t)r0 * N + col)       = make_float2(c0, c1);
            *(float2*)(C + (size_t)(r0 + 8) * N + col) = make_float2(c2, c3);
        }
    }
}

// ---------------------------------------------------------------------------
// Small FFMA SGEMM (two tiny ctx GEMMs; exact fp32).
// ---------------------------------------------------------------------------
template <bool TANH>
__global__ __launch_bounds__(256) void sgemm_kernel(
    const float* __restrict__ Ab, const float* __restrict__ Bb,
    float* __restrict__ Cb,
    int M, int N, int K,
    long long sA, long long sB, long long sC)
{
    const float* A = Ab + (size_t)blockIdx.z * sA;
    const float* B = Bb + (size_t)blockIdx.z * sB;
    float*       C = Cb + (size_t)blockIdx.z * sC;

    __shared__ float As[8][128];
    __shared__ float Bs[8][128];

    const int tid = threadIdx.x;
    const int m0  = blockIdx.y * 128;
    const int n0  = blockIdx.x * 128;
    const int tx = tid & 15;
    const int ty = tid >> 4;
    const int brow = tid >> 5;
    const int bcol = (tid & 31) * 4;
    const int arow = tid >> 1;
    const int acol = (tid & 1) * 4;

    float acc[8][8];
#pragma unroll
    for (int i = 0; i < 8; i++)
#pragma unroll
        for (int j = 0; j < 8; j++) acc[i][j] = 0.f;

    for (int k0 = 0; k0 < K; k0 += 8) {
        float4 a = *(const float4*)(A + (size_t)(m0 + arow) * K + k0 + acol);
        As[acol + 0][arow] = a.x;
        As[acol + 1][arow] = a.y;
        As[acol + 2][arow] = a.z;
        As[acol + 3][arow] = a.w;
        float4 b = *(const float4*)(B + (size_t)(k0 + brow) * N + n0 + bcol);
        *(float4*)&Bs[brow][bcol] = b;
        __syncthreads();
#pragma unroll
        for (int kk = 0; kk < 8; kk++) {
            float ar[8], br[8];
            *(float4*)&ar[0] = *(float4*)&As[kk][ty * 8];
            *(float4*)&ar[4] = *(float4*)&As[kk][ty * 8 + 4];
            *(float4*)&br[0] = *(float4*)&Bs[kk][tx * 8];
            *(float4*)&br[4] = *(float4*)&Bs[kk][tx * 8 + 4];
#pragma unroll
            for (int i = 0; i < 8; i++)
#pragma unroll
                for (int j = 0; j < 8; j++) acc[i][j] += ar[i] * br[j];
        }
        __syncthreads();
    }
#pragma unroll
    for (int i = 0; i < 8; i++) {
        size_t base = (size_t)(m0 + ty * 8 + i) * N + n0 + tx * 8;
        float4 v0, v1;
        if (TANH) {
            v0.x = tanhf(acc[i][0]); v0.y = tanhf(acc[i][1]);
            v0.z = tanhf(acc[i][2]); v0.w = tanhf(acc[i][3]);
            v1.x = tanhf(acc[i][4]); v1.y = tanhf(acc[i][5]);
            v1.z = tanhf(acc[i][6]); v1.w = tanhf(acc[i][7]);
        } else {
            v0.x = acc[i][0]; v0.y = acc[i][1]; v0.z = acc[i][2]; v0.w = acc[i][3];
            v1.x = acc[i][4]; v1.y = acc[i][5]; v1.z = acc[i][6]; v1.w = acc[i][7];
        }
        *(float4*)(C + base)     = v0;
        *(float4*)(C + base + 4) = v1;
    }
}

// ---------------------------------------------------------------------------
// Softmax over L=256 (in place), one block per row.
// ---------------------------------------------------------------------------
__global__ __launch_bounds__(256) void softmax_rows256(float* __restrict__ data)
{
    const size_t row = blockIdx.x;
    const int t = threadIdx.x;
    float v = data[row * LL + t];

    __shared__ float red[8];
    float m = v;
#pragma unroll
    for (int o = 16; o; o >>= 1) m = fmaxf(m, __shfl_xor_sync(0xffffffffu, m, o));
    if ((t & 31) == 0) red[t >> 5] = m;
    __syncthreads();
    if (t < 8) {
        float x = red[t];
#pragma unroll
        for (int o = 4; o; o >>= 1) x = fmaxf(x, __shfl_xor_sync(0xffu, x, o));
        if (t == 0) red[0] = x;
    }
    __syncthreads();
    m = red[0];
    float e = expf(v - m);
    __syncthreads();
    float s = e;
#pragma unroll
    for (int o = 16; o; o >>= 1) s += __shfl_xor_sync(0xffffffffu, s, o);
    if ((t & 31) == 0) red[t >> 5] = s;
    __syncthreads();
    if (t < 8) {
        float x = red[t];
#pragma unroll
        for (int o = 4; o; o >>= 1) x += __shfl_xor_sync(0xffu, x, o);
        if (t == 0) red[0] = x;
    }
    __syncthreads();
    data[row * LL + t] = e / red[0];
}

// ---------------------------------------------------------------------------
// Second softmax (over Q): partial sum-exp, reduce to reciprocal.
// ---------------------------------------------------------------------------
__global__ __launch_bounds__(256) void sumexp_partial_kernel()
{
    const int b = blockIdx.x;
    const int chunk = blockIdx.y;
    const int l = threadIdx.x;
    const size_t base = ((size_t)b * QQ + (size_t)chunk * 256) * LL + l;
    float s = 0.f;
#pragma unroll 8
    for (int q = 0; q < 256; q++) s += expf(g_attn[base + (size_t)q * LL]);
    g_partial[(b * 16 + chunk) * LL + l] = s;
}

__global__ __launch_bounds__(256) void sumexp_reduce_kernel()
{
    const int b = blockIdx.x;
    const int l = threadIdx.x;
    float s = 0.f;
#pragma unroll
    for (int c = 0; c < 16; c++) s += g_partial[(b * 16 + c) * LL + l];
    g_rsums[b * LL + l] = 1.0f / s;
}

// ---------------------------------------------------------------------------
// Finalize: exp * (1/sum) * combine, transposed into attn_map [b][l][q].
// ---------------------------------------------------------------------------
__global__ __launch_bounds__(256) void finalize_kernel(float* __restrict__ out_am)
{
    const int b  = blockIdx.y;
    const int q0 = blockIdx.x * 32;
    const int tx = threadIdx.x;
    const int ty = threadIdx.y;

    __shared__ float tile[32][33];

    for (int l0 = 0; l0 < LL; l0 += 32) {
        const float rs_col = g_rsums[b * LL + l0 + tx];
#pragma unroll
        for (int r = 0; r < 4; r++) {
            const int q = q0 + ty + 8 * r;
            const size_t idx = ((size_t)b * QQ + q) * LL + l0 + tx;
            tile[ty + 8 * r][tx] = expf(g_attn[idx]) * rs_col * g_combine[idx];
        }
        __syncthreads();
#pragma unroll
        for (int r = 0; r < 4; r++) {
            const int l = l0 + ty + 8 * r;
            out_am[((size_t)b * LL + l) * QQ + q0 + tx] = tile[tx][ty + 8 * r];
        }
        __syncthreads();
    }
}

// ---------------------------------------------------------------------------
// Launcher
// ---------------------------------------------------------------------------
extern "C" void kernel_launch(void* const* d_in, const int* in_sizes, int n_in,
                              void* d_out, int out_size)
{
    const float* x         = (const float*)d_in[0];
    const float* context   = (const float*)d_in[1];
    const float* w_context = (const float*)d_in[2];
    const float* w_img     = (const float*)d_in[3];
    const float* w_text    = (const float*)d_in[4];

    float* out_wc = (float*)d_out;
    float* out_am = out_wc + WC_ELEMS;

    float *p_source, *p_text, *p_img, *p_attn, *p_combine;
    cudaGetSymbolAddress((void**)&p_source,  g_source);
    cudaGetSymbolAddress((void**)&p_text,    g_text);
    cudaGetSymbolAddress((void**)&p_img,     g_img);
    cudaGetSymbolAddress((void**)&p_attn,    g_attn);
    cudaGetSymbolAddress((void**)&p_combine, g_combine);

    const long long sCTX = (long long)CDF_ * LL;
    const long long sSL  = (long long)IDF_ * LL;
    const long long sIQ  = (long long)IDF_ * QQ;
    const long long sQL  = (long long)QQ * LL;

    // 1) source = W_ctx @ ctx (exact fp32, feeds attn logits)
    sgemm_kernel<false><<<dim3(2, 4, BB), 256>>>(
        w_context, context, p_source, IDF_, LL, CDF_, 0, sCTX, sSL);
    // 2) text = tanh(W_text @ ctx)
    sgemm_kernel<true><<<dim3(2, 4, BB), 256>>>(
        w_text, context, p_text, IDF_, LL, CDF_, 0, sCTX, sSL);
    // 3) img = tanh(W_img @ x)  — tensor, 3xFP16, cp.async pipelined
    tgemm_kernel<true, false><<<dim3(32, 4, BB), 256>>>(
        w_img, x, p_img, IDF_, QQ, IDF_, 0, sIQ, sIQ);
    // 4) attn = x^T @ source    — tensor, 3xFP16, cp.async pipelined
    tgemm_kernel<false, true><<<dim3(2, 32, BB), 256>>>(
        x, p_source, p_attn, QQ, LL, IDF_, sIQ, sSL, sQL);
    // 5) combine = tanh(img^T @ text)
    tgemm_kernel<true, true><<<dim3(2, 32, BB), 256>>>(
        p_img, p_text, p_combine, QQ, LL, IDF_, sIQ, sSL, sQL);
    // 6) softmax over L
    softmax_rows256<<<BB * QQ, 256>>>(p_attn);
    // 7) second softmax over Q
    sumexp_partial_kernel<<<dim3(BB, 16), 256>>>();
    sumexp_reduce_kernel<<<BB, 256>>>();
    // 8) finalize into attn_map [b][l][q]
    finalize_kernel<<<dim3(QQ / 32, BB), dim3(32, 8)>>>(out_am);
    // 9) weighted_context = source @ attn_map
    tgemm_kernel<false, false><<<dim3(32, 4, BB), 256>>>(
        p_source, out_am, out_wc, IDF_, QQ, LL, sSL, (long long)LL * QQ, sIQ);
}